// round 2
// baseline (speedup 1.0000x reference)
#include <cuda_runtime.h>

// ---------------- problem constants ----------------
#define HID    2048
#define NHEADS 16
#define HD     128
#define BATCH  2
#define SEQ    2048
#define MROWS  (BATCH*SEQ)          // 4096
#define NSELF  8                    // n_self fixed at 8 by setup_inputs

// ---------------- scratch (device globals; allocation-free) ----------------
__device__ float g_q[MROWS * HID];                    // 32 MB
__device__ float g_k[MROWS * HID];                    // 32 MB
__device__ float g_v[MROWS * HID];                    // 32 MB
__device__ float g_o[MROWS * HID];                    // 32 MB
__device__ float g_wsum[HID * HID];                   // 16 MB
__device__ float g_scores[BATCH * NHEADS * SEQ * SEQ];// 512 MB

// ---------------- 128x128x8 SGEMM, 8x8 microtile, 256 threads ----------------
#define TBM 128
#define TBN 128
#define TBK 8

// C = alpha * A @ B^T ; A: MxK row-major, B: NxK row-major, C: MxN
// batched over blockIdx.z -> (b = z/H, h = z%H)
__global__ void __launch_bounds__(256, 2)
gemm_nt(const float* __restrict__ A, const float* __restrict__ B,
        float* __restrict__ C, int K,
        int lda, int ldb, int ldc,
        int H, long sAb, long sAh, long sBb, long sBh,
        long sCb, long sCh, float alpha)
{
    int z = blockIdx.z;
    int b = z / H, h = z % H;
    A += (long)b * sAb + (long)h * sAh;
    B += (long)b * sBb + (long)h * sBh;
    C += (long)b * sCb + (long)h * sCh;

    __shared__ float As[TBK][TBM + 4];
    __shared__ float Bs[TBK][TBN + 4];

    int tid = threadIdx.x;
    int loadRow = tid >> 1;         // 0..127
    int loadK   = (tid & 1) * 4;    // 0 or 4
    int rowBase = blockIdx.y * TBM;
    int colBase = blockIdx.x * TBN;
    int trow = tid >> 4;            // 0..15
    int tcol = tid & 15;            // 0..15

    const float* Ap = A + (long)(rowBase + loadRow) * lda + loadK;
    const float* Bp = B + (long)(colBase + loadRow) * ldb + loadK;

    float acc[8][8] = {};

    for (int k0 = 0; k0 < K; k0 += TBK) {
        float4 av = *(const float4*)(Ap + k0);
        As[loadK + 0][loadRow] = av.x; As[loadK + 1][loadRow] = av.y;
        As[loadK + 2][loadRow] = av.z; As[loadK + 3][loadRow] = av.w;
        float4 bv = *(const float4*)(Bp + k0);
        Bs[loadK + 0][loadRow] = bv.x; Bs[loadK + 1][loadRow] = bv.y;
        Bs[loadK + 2][loadRow] = bv.z; Bs[loadK + 3][loadRow] = bv.w;
        __syncthreads();
        #pragma unroll
        for (int kk = 0; kk < TBK; kk++) {
            float a[8], bb[8];
            #pragma unroll
            for (int i = 0; i < 8; i++) a[i]  = As[kk][trow * 8 + i];
            #pragma unroll
            for (int j = 0; j < 8; j++) bb[j] = Bs[kk][tcol * 8 + j];
            #pragma unroll
            for (int i = 0; i < 8; i++)
                #pragma unroll
                for (int j = 0; j < 8; j++)
                    acc[i][j] += a[i] * bb[j];
        }
        __syncthreads();
    }

    #pragma unroll
    for (int i = 0; i < 8; i++) {
        float* cp = C + (long)(rowBase + trow * 8 + i) * ldc + colBase + tcol * 8;
        float4 c0 = { alpha*acc[i][0], alpha*acc[i][1], alpha*acc[i][2], alpha*acc[i][3] };
        float4 c1 = { alpha*acc[i][4], alpha*acc[i][5], alpha*acc[i][6], alpha*acc[i][7] };
        *(float4*)cp       = c0;
        *(float4*)(cp + 4) = c1;
    }
}

// C = A @ B ; A: MxK row-major, B: KxN row-major, C: MxN
__global__ void __launch_bounds__(256, 2)
gemm_nn(const float* __restrict__ A, const float* __restrict__ B,
        float* __restrict__ C, int K,
        int lda, int ldb, int ldc,
        int H, long sAb, long sAh, long sBb, long sBh,
        long sCb, long sCh)
{
    int z = blockIdx.z;
    int b = z / H, h = z % H;
    A += (long)b * sAb + (long)h * sAh;
    B += (long)b * sBb + (long)h * sBh;
    C += (long)b * sCb + (long)h * sCh;

    __shared__ float As[TBK][TBM + 4];
    __shared__ float Bs[TBK][TBN + 4];

    int tid = threadIdx.x;
    int loadRow = tid >> 1;         // A: 0..127
    int loadK   = (tid & 1) * 4;    // A: k offset
    int bRow = tid >> 5;            // B: 0..7 (k rows)
    int bCol = (tid & 31) * 4;      // B: 0..124
    int rowBase = blockIdx.y * TBM;
    int colBase = blockIdx.x * TBN;
    int trow = tid >> 4;
    int tcol = tid & 15;

    const float* Ap = A + (long)(rowBase + loadRow) * lda + loadK;

    float acc[8][8] = {};

    for (int k0 = 0; k0 < K; k0 += TBK) {
        float4 av = *(const float4*)(Ap + k0);
        As[loadK + 0][loadRow] = av.x; As[loadK + 1][loadRow] = av.y;
        As[loadK + 2][loadRow] = av.z; As[loadK + 3][loadRow] = av.w;
        float4 bv = *(const float4*)(B + (long)(k0 + bRow) * ldb + colBase + bCol);
        Bs[bRow][bCol + 0] = bv.x; Bs[bRow][bCol + 1] = bv.y;
        Bs[bRow][bCol + 2] = bv.z; Bs[bRow][bCol + 3] = bv.w;
        __syncthreads();
        #pragma unroll
        for (int kk = 0; kk < TBK; kk++) {
            float a[8], bb[8];
            #pragma unroll
            for (int i = 0; i < 8; i++) a[i]  = As[kk][trow * 8 + i];
            #pragma unroll
            for (int j = 0; j < 8; j++) bb[j] = Bs[kk][tcol * 8 + j];
            #pragma unroll
            for (int i = 0; i < 8; i++)
                #pragma unroll
                for (int j = 0; j < 8; j++)
                    acc[i][j] += a[i] * bb[j];
        }
        __syncthreads();
    }

    #pragma unroll
    for (int i = 0; i < 8; i++) {
        float* cp = C + (long)(rowBase + trow * 8 + i) * ldc + colBase + tcol * 8;
        float4 c0 = { acc[i][0], acc[i][1], acc[i][2], acc[i][3] };
        float4 c1 = { acc[i][4], acc[i][5], acc[i][6], acc[i][7] };
        *(float4*)cp       = c0;
        *(float4*)(cp + 4) = c1;
    }
}

// ---------------- 0.5*(Wo_self + Wo_cross) ----------------
__global__ void wsum_kernel(float* __restrict__ W, const float* __restrict__ A,
                            const float* __restrict__ Bm, int n)
{
    int i = blockIdx.x * blockDim.x + threadIdx.x;
    if (i < n) W[i] = 0.5f * (A[i] + Bm[i]);
}

// ---------------- RoPE (in-place, all heads) ----------------
__global__ void rope_kernel(float* __restrict__ X)
{
    long idx = (long)blockIdx.x * blockDim.x + threadIdx.x;
    int d = (int)(idx & 63);
    int h = (int)((idx >> 6) & (NHEADS - 1));
    long row = idx >> 10;               // b*SEQ + s
    int s = (int)(row & (SEQ - 1));
    long base = row * HID + h * HD + d;

    float invf = expf((float)d * (-2.0f / 128.0f) * 9.210340371976184f);
    float ang = (float)s * invf;
    float c = cosf(ang), sn = sinf(ang);

    float x1 = X[base];
    float x2 = X[base + 64];
    X[base]      = x1 * c - x2 * sn;
    X[base + 64] = x2 * c + x1 * sn;
}

// ---------------- row softmax over 2048 ----------------
__global__ void softmax_rows(float* __restrict__ Sc)
{
    float* row = Sc + (long)blockIdx.x * SEQ;
    int t = threadIdx.x;
    float v[8];
    float m = -1e30f;
    #pragma unroll
    for (int i = 0; i < 8; i++) { v[i] = row[t + i * 256]; m = fmaxf(m, v[i]); }

    __shared__ float red[8];
    #pragma unroll
    for (int off = 16; off; off >>= 1) m = fmaxf(m, __shfl_xor_sync(0xffffffffu, m, off));
    if ((t & 31) == 0) red[t >> 5] = m;
    __syncthreads();
    float bm = red[0];
    #pragma unroll
    for (int i = 1; i < 8; i++) bm = fmaxf(bm, red[i]);

    float s = 0.f;
    #pragma unroll
    for (int i = 0; i < 8; i++) { v[i] = expf(v[i] - bm); s += v[i]; }
    #pragma unroll
    for (int off = 16; off; off >>= 1) s += __shfl_xor_sync(0xffffffffu, s, off);
    __syncthreads();
    if ((t & 31) == 0) red[t >> 5] = s;
    __syncthreads();
    float bs = 0.f;
    #pragma unroll
    for (int i = 0; i < 8; i++) bs += red[i];
    float r = 1.0f / bs;
    #pragma unroll
    for (int i = 0; i < 8; i++) row[t + i * 256] = v[i] * r;
}

// ---------------- launch ----------------
extern "C" void kernel_launch(void* const* d_in, const int* in_sizes, int n_in,
                              void* d_out, int out_size)
{
    const float* x_q      = (const float*)d_in[0];
    const float* x_kv     = (const float*)d_in[1];
    const float* Wq       = (const float*)d_in[2];
    const float* Wk_self  = (const float*)d_in[3];
    const float* Wv_self  = (const float*)d_in[4];
    const float* Wk_cross = (const float*)d_in[5];
    const float* Wv_cross = (const float*)d_in[6];
    const float* Wo_self  = (const float*)d_in[7];
    const float* Wo_cross = (const float*)d_in[8];
    float* out = (float*)d_out;

    float *q, *k, *v, *o, *ws, *sc;
    cudaGetSymbolAddress((void**)&q,  g_q);
    cudaGetSymbolAddress((void**)&k,  g_k);
    cudaGetSymbolAddress((void**)&v,  g_v);
    cudaGetSymbolAddress((void**)&o,  g_o);
    cudaGetSymbolAddress((void**)&ws, g_wsum);
    cudaGetSymbolAddress((void**)&sc, g_scores);

    const float scale = 0.08838834764831845f;   // 1/sqrt(128)
    const long  SB  = (long)SEQ * HID;
    const long  SS2 = (long)SEQ * SEQ;
    const int   SPLIT = NSELF * HD;             // 1024

    // 0) output weight fold
    wsum_kernel<<<(HID * HID + 255) / 256, 256>>>(ws, Wo_self, Wo_cross, HID * HID);

    // 1) Q = x_q @ Wq^T
    gemm_nt<<<dim3(HID / TBN, MROWS / TBM, 1), 256>>>(
        x_q, Wq, q, HID, HID, HID, HID, 1, 0, 0, 0, 0, 0, 0, 1.0f);

    // 2) K: self half (heads 0..7) from x_q, cross half (heads 8..15) from x_kv
    gemm_nt<<<dim3(SPLIT / TBN, MROWS / TBM, 1), 256>>>(
        x_q, Wk_self, k, HID, HID, HID, HID, 1, 0, 0, 0, 0, 0, 0, 1.0f);
    gemm_nt<<<dim3(SPLIT / TBN, MROWS / TBM, 1), 256>>>(
        x_kv, Wk_cross + (long)SPLIT * HID, k + SPLIT,
        HID, HID, HID, HID, 1, 0, 0, 0, 0, 0, 0, 1.0f);

    // 3) V: same split
    gemm_nt<<<dim3(SPLIT / TBN, MROWS / TBM, 1), 256>>>(
        x_q, Wv_self, v, HID, HID, HID, HID, 1, 0, 0, 0, 0, 0, 0, 1.0f);
    gemm_nt<<<dim3(SPLIT / TBN, MROWS / TBM, 1), 256>>>(
        x_kv, Wv_cross + (long)SPLIT * HID, v + SPLIT,
        HID, HID, HID, HID, 1, 0, 0, 0, 0, 0, 0, 1.0f);

    // 4) RoPE on Q and K
    {
        long n = (long)MROWS * NHEADS * 64;
        rope_kernel<<<(unsigned)(n / 256), 256>>>(q);
        rope_kernel<<<(unsigned)(n / 256), 256>>>(k);
    }

    // 5) scores[b,h] = scale * Q_h @ K_h^T
    gemm_nt<<<dim3(SEQ / TBN, SEQ / TBM, BATCH * NHEADS), 256>>>(
        q, k, sc, HD, HID, HID, SEQ,
        NHEADS, SB, (long)HD, SB, (long)HD,
        (long)NHEADS * SS2, SS2, scale);

    // 6) softmax over each of the 32*2048 rows
    softmax_rows<<<BATCH * NHEADS * SEQ, 256>>>(sc);

    // 7) O_h = P @ V_h
    gemm_nn<<<dim3(HD / TBN, SEQ / TBM, BATCH * NHEADS), 256>>>(
        sc, v, o, SEQ, SEQ, HID, HID,
        NHEADS, (long)NHEADS * SS2, SS2, SB, (long)HD, SB, (long)HD);

    // 8) out = O_flat @ Wsum^T
    gemm_nt<<<dim3(HID / TBN, MROWS / TBM, 1), 256>>>(
        o, ws, out, HID, HID, HID, HID, 1, 0, 0, 0, 0, 0, 0, 1.0f);
}

// round 6
// speedup vs baseline: 2.8634x; 2.8634x over previous
#include <cuda_runtime.h>
#include <cstdint>

// ---------------- problem constants ----------------
#define HID    2048
#define NHEADS 16
#define HD     128
#define BATCH  2
#define SEQ    2048
#define MROWS  (BATCH*SEQ)          // 4096
#define NSELF  8

// ---------------- scratch (device globals; allocation-free) ----------------
__device__ float g_q[MROWS * HID];
__device__ float g_k[MROWS * HID];
__device__ float g_v[MROWS * HID];
__device__ float g_o[MROWS * HID];
__device__ float g_wsum[HID * HID];
__device__ float g_scores[(long)BATCH * NHEADS * SEQ * SEQ];   // 512 MB
// tf32-rounded operand copies
__device__ float g_xq[MROWS * HID];
__device__ float g_xkv[MROWS * HID];
__device__ float g_wq[HID * HID];
__device__ float g_wk[HID * HID];   // rows [0,1024) self, [1024,2048) cross
__device__ float g_wv[HID * HID];

// ---------------- helpers ----------------
__device__ __forceinline__ float to_tf32(float x) {
    unsigned u;
    asm("cvt.rna.tf32.f32 %0, %1;" : "=r"(u) : "f"(x));
    return __uint_as_float(u);
}

__device__ __forceinline__ void cp_async16(void* smem, const void* gmem) {
    unsigned s = (unsigned)__cvta_generic_to_shared(smem);
    asm volatile("cp.async.cg.shared.global [%0], [%1], 16;" :: "r"(s), "l"(gmem));
}

__device__ __forceinline__ void mma_tf32(float* c, const uint32_t* a, const uint32_t* b) {
    asm volatile(
        "mma.sync.aligned.m16n8k8.row.col.f32.tf32.tf32.f32 "
        "{%0,%1,%2,%3}, {%4,%5,%6,%7}, {%8,%9}, {%0,%1,%2,%3};\n"
        : "+f"(c[0]), "+f"(c[1]), "+f"(c[2]), "+f"(c[3])
        : "r"(a[0]), "r"(a[1]), "r"(a[2]), "r"(a[3]), "r"(b[0]), "r"(b[1]));
}

// ---------------- tf32 tensor-core GEMM (static smem, BK=16, double buffer) ----
// NT=true : C = alpha * A(MxK,row) @ B(NxK,row)^T
// NT=false: C = alpha * A(MxK,row) @ B(KxN,row)
// batched over blockIdx.z -> (b = z/H, h = z%H)
#define GBM 128
#define GBN 128
#define GBK 16
#define AS_ST 20        // floats: 16 + 4 pad
#define BS_ST_NT 20
#define BS_ST_NN 136    // floats: 128 + 8 pad (8*tig+gid -> conflict-free)

template<bool NT>
__global__ void __launch_bounds__(256)
mma_gemm(const float* __restrict__ A, const float* __restrict__ B,
         float* __restrict__ C, int K,
         int lda, int ldb, int ldc, int H,
         long sAb, long sAh, long sBb, long sBh, long sCb, long sCh,
         float alpha, int cvtOut)
{
    constexpr int ASZ = GBM * AS_ST;                                  // 2560
    constexpr int BSZ = NT ? (GBN * BS_ST_NT) : (GBK * BS_ST_NN);     // 2560 / 2176
    __shared__ float As_s[2 * ASZ];
    __shared__ float Bs_s[2 * BSZ];

    int z = blockIdx.z;
    int b = z / H, h = z - b * H;
    A += (long)b * sAb + (long)h * sAh;
    B += (long)b * sBb + (long)h * sBh;
    C += (long)b * sCb + (long)h * sCh;

    const int tid  = threadIdx.x;
    const int lane = tid & 31, warp = tid >> 5;
    const int wm = warp & 1, wn = warp >> 1;               // 2 x 4 warp grid
    const int gid = lane >> 2, tig = lane & 3;
    const long rowBase = (long)blockIdx.y * GBM;
    const long colBase = (long)blockIdx.x * GBN;

    const int aRow = tid >> 2;            // 0..63
    const int aK4  = (tid & 3) * 4;       // 0,4,8,12
    const int bK   = tid >> 5;            // 0..7   (NN)
    const int bN4  = (tid & 31) * 4;      // 0..124 (NN)

    const float* Ag   = A + (rowBase + aRow) * lda + aK4;
    const float* BgNT = B + (colBase + aRow) * ldb + aK4;
    const float* BgNN = B + colBase + bN4;

    float acc[4][4][4];
    #pragma unroll
    for (int i = 0; i < 4; i++)
        #pragma unroll
        for (int j = 0; j < 4; j++)
            #pragma unroll
            for (int r = 0; r < 4; r++) acc[i][j][r] = 0.f;

    const int ntile = K >> 4;

    auto loadTile = [&](int t, int buf) {
        float* As = As_s + buf * ASZ;
        float* Bs = Bs_s + buf * BSZ;
        const int k0 = t << 4;
        #pragma unroll
        for (int i = 0; i < 2; i++)
            cp_async16(&As[(aRow + 64 * i) * AS_ST + aK4],
                       Ag + (long)(64 * i) * lda + k0);
        if (NT) {
            #pragma unroll
            for (int i = 0; i < 2; i++)
                cp_async16(&Bs[(aRow + 64 * i) * BS_ST_NT + aK4],
                           BgNT + (long)(64 * i) * ldb + k0);
        } else {
            #pragma unroll
            for (int i = 0; i < 2; i++)
                cp_async16(&Bs[(bK + 8 * i) * BS_ST_NN + bN4],
                           BgNN + (long)(k0 + bK + 8 * i) * ldb);
        }
        asm volatile("cp.async.commit_group;\n" ::: "memory");
    };

    auto compute = [&](int buf) {
        float* As = As_s + buf * ASZ;
        float* Bs = Bs_s + buf * BSZ;
        #pragma unroll
        for (int kk = 0; kk < GBK; kk += 8) {
            uint32_t af[4][4], bf[4][2];
            #pragma unroll
            for (int mt = 0; mt < 4; mt++) {
                const float* p = As + (wm * 64 + mt * 16 + gid) * AS_ST + kk + tig;
                af[mt][0] = __float_as_uint(p[0]);
                af[mt][1] = __float_as_uint(p[8 * AS_ST]);
                af[mt][2] = __float_as_uint(p[4]);
                af[mt][3] = __float_as_uint(p[8 * AS_ST + 4]);
            }
            #pragma unroll
            for (int nt = 0; nt < 4; nt++) {
                if (NT) {
                    const float* p = Bs + (wn * 32 + nt * 8 + gid) * BS_ST_NT + kk + tig;
                    bf[nt][0] = __float_as_uint(p[0]);
                    bf[nt][1] = __float_as_uint(p[4]);
                } else {
                    const float* p = Bs + (kk + tig) * BS_ST_NN + wn * 32 + nt * 8 + gid;
                    bf[nt][0] = __float_as_uint(p[0]);
                    bf[nt][1] = __float_as_uint(p[4 * BS_ST_NN]);
                }
            }
            #pragma unroll
            for (int mt = 0; mt < 4; mt++)
                #pragma unroll
                for (int nt = 0; nt < 4; nt++)
                    mma_tf32(acc[mt][nt], af[mt], bf[nt]);
        }
    };

    loadTile(0, 0);
    for (int t = 0; t < ntile; t++) {
        if (t + 1 < ntile) {
            loadTile(t + 1, (t + 1) & 1);
            asm volatile("cp.async.wait_group 1;\n" ::: "memory");
        } else {
            asm volatile("cp.async.wait_group 0;\n" ::: "memory");
        }
        __syncthreads();
        compute(t & 1);
        __syncthreads();
    }

    #pragma unroll
    for (int mt = 0; mt < 4; mt++) {
        long r0 = rowBase + wm * 64 + mt * 16 + gid;
        #pragma unroll
        for (int nt = 0; nt < 4; nt++) {
            long c0 = colBase + wn * 32 + nt * 8 + tig * 2;
            float v0 = alpha * acc[mt][nt][0];
            float v1 = alpha * acc[mt][nt][1];
            float v2 = alpha * acc[mt][nt][2];
            float v3 = alpha * acc[mt][nt][3];
            if (cvtOut) {
                v0 = to_tf32(v0); v1 = to_tf32(v1);
                v2 = to_tf32(v2); v3 = to_tf32(v3);
            }
            float2 w0 = {v0, v1}, w1 = {v2, v3};
            *(float2*)&C[r0 * ldc + c0]       = w0;
            *(float2*)&C[(r0 + 8) * ldc + c0] = w1;
        }
    }
}

// ---------------- elementwise kernels ----------------
__global__ void cvt_copy(float* __restrict__ dst, const float* __restrict__ src, long n4)
{
    long i = (long)blockIdx.x * blockDim.x + threadIdx.x;
    if (i < n4) {
        float4 v = ((const float4*)src)[i];
        v.x = to_tf32(v.x); v.y = to_tf32(v.y);
        v.z = to_tf32(v.z); v.w = to_tf32(v.w);
        ((float4*)dst)[i] = v;
    }
}

__global__ void wsum_kernel(float* __restrict__ W, const float* __restrict__ A,
                            const float* __restrict__ Bm, int n)
{
    int i = blockIdx.x * blockDim.x + threadIdx.x;
    if (i < n) W[i] = to_tf32(0.5f * (A[i] + Bm[i]));
}

// RoPE in-place on all heads; rounds outputs to tf32 (feeds scores GEMM).
__global__ void rope_kernel(float* __restrict__ X)
{
    long idx = (long)blockIdx.x * blockDim.x + threadIdx.x;
    int d = (int)(idx & 63);
    long row = idx >> 10;                 // b*SEQ + s
    int h = (int)((idx >> 6) & (NHEADS - 1));
    int s = (int)(row & (SEQ - 1));
    long base = row * HID + h * HD + d;

    float invf = expf((float)d * (-2.0f / 128.0f) * 9.210340371976184f);
    float ang = (float)s * invf;
    float c = cosf(ang), sn = sinf(ang);

    float x1 = X[base];
    float x2 = X[base + 64];
    X[base]      = to_tf32(x1 * c - x2 * sn);
    X[base + 64] = to_tf32(x2 * c + x1 * sn);
}

// row softmax over 2048; rounds P to tf32 (feeds PV GEMM).
__global__ void softmax_rows(float* __restrict__ Sc)
{
    float* row = Sc + (long)blockIdx.x * SEQ;
    int t = threadIdx.x;
    float v[8];
    float m = -1e30f;
    #pragma unroll
    for (int i = 0; i < 8; i++) { v[i] = row[t + i * 256]; m = fmaxf(m, v[i]); }

    __shared__ float red[8];
    #pragma unroll
    for (int off = 16; off; off >>= 1) m = fmaxf(m, __shfl_xor_sync(0xffffffffu, m, off));
    if ((t & 31) == 0) red[t >> 5] = m;
    __syncthreads();
    float bm = red[0];
    #pragma unroll
    for (int i = 1; i < 8; i++) bm = fmaxf(bm, red[i]);

    float s = 0.f;
    #pragma unroll
    for (int i = 0; i < 8; i++) { v[i] = expf(v[i] - bm); s += v[i]; }
    #pragma unroll
    for (int off = 16; off; off >>= 1) s += __shfl_xor_sync(0xffffffffu, s, off);
    __syncthreads();
    if ((t & 31) == 0) red[t >> 5] = s;
    __syncthreads();
    float bs = 0.f;
    #pragma unroll
    for (int i = 0; i < 8; i++) bs += red[i];
    float r = 1.0f / bs;
    #pragma unroll
    for (int i = 0; i < 8; i++) row[t + i * 256] = to_tf32(v[i] * r);
}

// ---------------- launch ----------------
extern "C" void kernel_launch(void* const* d_in, const int* in_sizes, int n_in,
                              void* d_out, int out_size)
{
    const float* x_q      = (const float*)d_in[0];
    const float* x_kv     = (const float*)d_in[1];
    const float* Wq       = (const float*)d_in[2];
    const float* Wk_self  = (const float*)d_in[3];
    const float* Wv_self  = (const float*)d_in[4];
    const float* Wk_cross = (const float*)d_in[5];
    const float* Wv_cross = (const float*)d_in[6];
    const float* Wo_self  = (const float*)d_in[7];
    const float* Wo_cross = (const float*)d_in[8];
    float* out = (float*)d_out;

    float *q, *k, *v, *o, *ws, *sc, *xq, *xkv, *wq, *wk, *wv;
    cudaGetSymbolAddress((void**)&q,   g_q);
    cudaGetSymbolAddress((void**)&k,   g_k);
    cudaGetSymbolAddress((void**)&v,   g_v);
    cudaGetSymbolAddress((void**)&o,   g_o);
    cudaGetSymbolAddress((void**)&ws,  g_wsum);
    cudaGetSymbolAddress((void**)&sc,  g_scores);
    cudaGetSymbolAddress((void**)&xq,  g_xq);
    cudaGetSymbolAddress((void**)&xkv, g_xkv);
    cudaGetSymbolAddress((void**)&wq,  g_wq);
    cudaGetSymbolAddress((void**)&wk,  g_wk);
    cudaGetSymbolAddress((void**)&wv,  g_wv);

    const float scale = 0.08838834764831845f;   // 1/sqrt(128)
    const long  SB  = (long)SEQ * HID;
    const long  SS2 = (long)SEQ * SEQ;
    const int   SPLIT = NSELF * HD;             // 1024
    const long  HALF_W = (long)SPLIT * HID;     // 1024*2048

    // 0) tf32-round inputs into scratch; fold output weights
    cvt_copy<<<(unsigned)((long)MROWS * HID / 4 / 256), 256>>>(xq,  x_q,  (long)MROWS * HID / 4);
    cvt_copy<<<(unsigned)((long)MROWS * HID / 4 / 256), 256>>>(xkv, x_kv, (long)MROWS * HID / 4);
    cvt_copy<<<(unsigned)((long)HID * HID / 4 / 256), 256>>>(wq, Wq, (long)HID * HID / 4);
    cvt_copy<<<(unsigned)(HALF_W / 4 / 256), 256>>>(wk,          Wk_self,           HALF_W / 4);
    cvt_copy<<<(unsigned)(HALF_W / 4 / 256), 256>>>(wk + HALF_W, Wk_cross + HALF_W, HALF_W / 4);
    cvt_copy<<<(unsigned)(HALF_W / 4 / 256), 256>>>(wv,          Wv_self,           HALF_W / 4);
    cvt_copy<<<(unsigned)(HALF_W / 4 / 256), 256>>>(wv + HALF_W, Wv_cross + HALF_W, HALF_W / 4);
    wsum_kernel<<<(HID * HID + 255) / 256, 256>>>(ws, Wo_self, Wo_cross, HID * HID);

    // 1) Q = xq @ Wq^T
    mma_gemm<true><<<dim3(HID / GBN, MROWS / GBM, 1), 256>>>(
        xq, wq, q, HID, HID, HID, HID, 1, 0, 0, 0, 0, 0, 0, 1.0f, 0);

    // 2) K halves (self from xq, cross from xkv)
    mma_gemm<true><<<dim3(SPLIT / GBN, MROWS / GBM, 1), 256>>>(
        xq, wk, k, HID, HID, HID, HID, 1, 0, 0, 0, 0, 0, 0, 1.0f, 0);
    mma_gemm<true><<<dim3(SPLIT / GBN, MROWS / GBM, 1), 256>>>(
        xkv, wk + HALF_W, k + SPLIT, HID, HID, HID, HID, 1, 0, 0, 0, 0, 0, 0, 1.0f, 0);

    // 3) V halves (round outputs: V feeds PV GEMM directly)
    mma_gemm<true><<<dim3(SPLIT / GBN, MROWS / GBM, 1), 256>>>(
        xq, wv, v, HID, HID, HID, HID, 1, 0, 0, 0, 0, 0, 0, 1.0f, 1);
    mma_gemm<true><<<dim3(SPLIT / GBN, MROWS / GBM, 1), 256>>>(
        xkv, wv + HALF_W, v + SPLIT, HID, HID, HID, HID, 1, 0, 0, 0, 0, 0, 0, 1.0f, 1);

    // 4) RoPE on Q and K (rounds outputs)
    {
        long n = (long)MROWS * NHEADS * 64;
        rope_kernel<<<(unsigned)(n / 256), 256>>>(q);
        rope_kernel<<<(unsigned)(n / 256), 256>>>(k);
    }

    // 5) scores[b,h] = scale * Q_h @ K_h^T
    mma_gemm<true><<<dim3(SEQ / GBN, SEQ / GBM, BATCH * NHEADS), 256>>>(
        q, k, sc, HD, HID, HID, SEQ,
        NHEADS, SB, (long)HD, SB, (long)HD,
        (long)NHEADS * SS2, SS2, scale, 0);

    // 6) softmax (rounds P)
    softmax_rows<<<BATCH * NHEADS * SEQ, 256>>>(sc);

    // 7) O_h = P @ V_h  (rounds outputs: O feeds final GEMM)
    mma_gemm<false><<<dim3(HD / GBN, SEQ / GBM, BATCH * NHEADS), 256>>>(
        sc, v, o, SEQ, SEQ, HID, HID,
        NHEADS, (long)NHEADS * SS2, SS2, SB, (long)HD, SB, (long)HD, 1.0f, 1);

    // 8) out = O_flat @ Wsum^T  (full fp32 output)
    mma_gemm<true><<<dim3(HID / GBN, MROWS / GBM, 1), 256>>>(
        o, ws, out, HID, HID, HID, HID, 1, 0, 0, 0, 0, 0, 0, 1.0f, 0);
}